// round 9
// baseline (speedup 1.0000x reference)
#include <cuda_runtime.h>
#include <cstdint>

// ---------------------------------------------------------------------------
// GCN via one-pass bucket-CSR gather, place || gemm via graph stream fork:
//   branch A: memsets, detect, place (bucket[dst*64+slot]=src; cur==degree)
//   branch B: p_raw = x @ W1            (independent of A)
//   gather1:  q[n] = dn*(dn*(sum_s dinv_s*praw[s] + dn*praw[n]) + b1)
//             (per-edge dinv computed from g_cur; q written pre-scaled)
//   gather2:  h[n] = dn*(sum q[s] + q[n]); pool[batch[n]] += h (red.v4)
//   head:     mean, @W2+b2, relu(@fcW1+fcb1), batchnorm, softplus(@fcW2+fcb2)
//             512 threads: lane pair (2g, 2g+1) splits the o2/z GEMMs.
// ---------------------------------------------------------------------------

#define MAXN 100000
#define MAXE 1600000
#define MAXG 256
#define C 32
#define CAP 64

__device__ int   g_bucket[MAXN * CAP];
__device__ int   g_cur[MAXN];          // placement cursor == degree afterwards
__device__ int   g_ovf_dst[MAXE];
__device__ int   g_ovf_src[MAXE];
__device__ int   g_ovf_cnt;
__device__ float g_p[MAXN * C];        // p_raw (unscaled x@W1)
__device__ float g_q[MAXN * C];        // layer-2 input, pre-scaled by dinv
__device__ float g_pool[MAXG * C];
__device__ int   g_flags[2];           // [0]=edge_index int64, [1]=batch int64

static inline int ceil_div(int a, int b) { return (a + b - 1) / b; }

// Host-side stream/event objects (created once; host objects, no device mem)
struct StreamPack {
    cudaStream_t s2;
    cudaEvent_t ev_fork, ev_join;
    StreamPack() {
        cudaStreamCreateWithFlags(&s2, cudaStreamNonBlocking);
        cudaEventCreateWithFlags(&ev_fork, cudaEventDisableTiming);
        cudaEventCreateWithFlags(&ev_join, cudaEventDisableTiming);
    }
};
static StreamPack g_sp;

__device__ __forceinline__ int idx_get(const void* p, long i, int is64) {
    return is64 ? (int)((const long long*)p)[i] : ((const int*)p)[i];
}

// ---------------------------------------------------------------------------
// dtype detect (zeroing handled by cudaMemsetAsync host-side)
// ---------------------------------------------------------------------------
__global__ void k_detect(const unsigned* __restrict__ e, long ewords,
                         const unsigned* __restrict__ b, long bwords) {
    __shared__ unsigned se, sb;
    if (threadIdx.x == 0) { se = 0u; sb = 0u; g_ovf_cnt = 0; }
    __syncthreads();
    unsigned a = 0u, c = 0u;
    long eh = ewords / 2, bh = bwords / 2;
    for (int s = 0; s < 16; s++) {
        long idx = (long)(threadIdx.x * 16 + s);
        long j = (idx * eh) / 4096;
        a |= e[2 * j + 1];
        long k = (idx * bh) / 4096;
        c |= b[2 * k + 1];
    }
    atomicOr(&se, a);
    atomicOr(&sb, c);
    __syncthreads();
    if (threadIdx.x == 0) {
        g_flags[0] = (se == 0u) ? 1 : 0;
        g_flags[1] = (sb == 0u) ? 1 : 0;
    }
}

// ---------------------------------------------------------------------------
// One-pass bucket placement, 2 independent edges/thread (batched).
// ---------------------------------------------------------------------------
__global__ void k_place(const void* __restrict__ eidx, int E) {
    int is64 = g_flags[0];
    int T = gridDim.x * blockDim.x;
    int tid = blockIdx.x * blockDim.x + threadIdx.x;

    int e0 = tid, e1 = tid + T;
    bool v0 = e0 < E, v1 = e1 < E;
    int s0 = 0, t0 = 0, s1 = 0, t1 = 0;
    if (v0) { s0 = idx_get(eidx, e0, is64); t0 = idx_get(eidx, (long)E + e0, is64); }
    if (v1) { s1 = idx_get(eidx, e1, is64); t1 = idx_get(eidx, (long)E + e1, is64); }

    int sl0 = 0, sl1 = 0;
    if (v0) sl0 = atomicAdd(&g_cur[t0], 1);
    if (v1) sl1 = atomicAdd(&g_cur[t1], 1);

    if (v0) {
        if (sl0 < CAP) g_bucket[(size_t)t0 * CAP + sl0] = s0;
        else { int o = atomicAdd(&g_ovf_cnt, 1); g_ovf_dst[o] = t0; g_ovf_src[o] = s0; }
    }
    if (v1) {
        if (sl1 < CAP) g_bucket[(size_t)t1 * CAP + sl1] = s1;
        else { int o = atomicAdd(&g_ovf_cnt, 1); g_ovf_dst[o] = t1; g_ovf_src[o] = s1; }
    }
}

// ---------------------------------------------------------------------------
// GEMM raw (packed fma.rn.f32x2): p_raw[n,:] = x[n,:] @ W1  (no dinv)
// ---------------------------------------------------------------------------
__global__ void __launch_bounds__(256) k_gemm1(const float* __restrict__ x,
                                               const float* __restrict__ W1, int N) {
    __shared__ unsigned long long sW[128 * 16];
    const unsigned long long* Wp = (const unsigned long long*)W1;
    for (int i = threadIdx.x; i < 128 * 16; i += 256) sW[i] = Wp[i];
    __syncthreads();

    int n = blockIdx.x * 256 + threadIdx.x;
    if (n >= N) return;

    unsigned long long acc[16];
#pragma unroll
    for (int j = 0; j < 16; j++) acc[j] = 0ull;

    const float4* xr = (const float4*)(x + (size_t)n * 128);
#pragma unroll 2
    for (int k4 = 0; k4 < 32; k4++) {
        float4 xv = __ldg(&xr[k4]);
        const float* xf = (const float*)&xv;
#pragma unroll
        for (int kk = 0; kk < 4; kk++) {
            unsigned xb = __float_as_uint(xf[kk]);
            unsigned long long xx;
            asm("mov.b64 %0, {%1, %1};" : "=l"(xx) : "r"(xb));
            const unsigned long long* wr = sW + (k4 * 4 + kk) * 16;
#pragma unroll
            for (int j = 0; j < 16; j++) {
                asm("fma.rn.f32x2 %0, %1, %2, %0;"
                    : "+l"(acc[j]) : "l"(xx), "l"(wr[j]));
            }
        }
    }
    unsigned long long* out = (unsigned long long*)(g_p + (size_t)n * C);
#pragma unroll
    for (int j = 0; j < 16; j++) out[j] = acc[j];
}

// ---------------------------------------------------------------------------
// Gather layer 1 (scaled): 8 threads/node, per-edge dinv from g_cur.
//   q[n] = dn*(dn*(Σ dinv_s*praw[s] + dn*praw[n]) + b1)
// ---------------------------------------------------------------------------
__global__ void __launch_bounds__(256) k_gather1(const float* __restrict__ b1, int N) {
    int node = blockIdx.x * 32 + (threadIdx.x >> 3);
    int lane = threadIdx.x & 7;
    if (node >= N) return;

    int deg = g_cur[node];
    int m = deg < CAP ? deg : CAP;
    const int4* bp4 = (const int4*)(g_bucket + (size_t)node * CAP);
    const float4* F = (const float4*)g_p;

    float dn = rsqrtf(1.0f + (float)deg);
    float4 s = __ldg(&F[(size_t)node * 8 + lane]);   // self praw
    float4 a0 = make_float4(s.x * dn, s.y * dn, s.z * dn, s.w * dn);
    float4 a1 = make_float4(0, 0, 0, 0);

    int e = 0;
    for (; e + 4 <= m; e += 4) {
        int4 ia = __ldg(&bp4[e >> 2]);
        int d0 = __ldg(&g_cur[ia.x]);
        int d1 = __ldg(&g_cur[ia.y]);
        int d2 = __ldg(&g_cur[ia.z]);
        int d3 = __ldg(&g_cur[ia.w]);
        float4 v0 = __ldg(&F[(size_t)ia.x * 8 + lane]);
        float4 v1 = __ldg(&F[(size_t)ia.y * 8 + lane]);
        float4 v2 = __ldg(&F[(size_t)ia.z * 8 + lane]);
        float4 v3 = __ldg(&F[(size_t)ia.w * 8 + lane]);
        float w0 = rsqrtf(1.0f + (float)d0);
        float w1 = rsqrtf(1.0f + (float)d1);
        float w2 = rsqrtf(1.0f + (float)d2);
        float w3 = rsqrtf(1.0f + (float)d3);
        a0.x = fmaf(v0.x, w0, a0.x); a0.y = fmaf(v0.y, w0, a0.y);
        a0.z = fmaf(v0.z, w0, a0.z); a0.w = fmaf(v0.w, w0, a0.w);
        a1.x = fmaf(v1.x, w1, a1.x); a1.y = fmaf(v1.y, w1, a1.y);
        a1.z = fmaf(v1.z, w1, a1.z); a1.w = fmaf(v1.w, w1, a1.w);
        a0.x = fmaf(v2.x, w2, a0.x); a0.y = fmaf(v2.y, w2, a0.y);
        a0.z = fmaf(v2.z, w2, a0.z); a0.w = fmaf(v2.w, w2, a0.w);
        a1.x = fmaf(v3.x, w3, a1.x); a1.y = fmaf(v3.y, w3, a1.y);
        a1.z = fmaf(v3.z, w3, a1.z); a1.w = fmaf(v3.w, w3, a1.w);
    }
    const int* bp = (const int*)bp4;
    for (; e < m; e++) {
        int i0 = __ldg(&bp[e]);
        int d0 = __ldg(&g_cur[i0]);
        float4 v0 = __ldg(&F[(size_t)i0 * 8 + lane]);
        float w0 = rsqrtf(1.0f + (float)d0);
        a0.x = fmaf(v0.x, w0, a0.x); a0.y = fmaf(v0.y, w0, a0.y);
        a0.z = fmaf(v0.z, w0, a0.z); a0.w = fmaf(v0.w, w0, a0.w);
    }
    if (deg > CAP) {   // exact overflow handling (normally empty)
        int oc = g_ovf_cnt;
        for (int i = 0; i < oc; i++) {
            if (g_ovf_dst[i] == node) {
                int sidx = g_ovf_src[i];
                float w = rsqrtf(1.0f + (float)__ldg(&g_cur[sidx]));
                float4 v = __ldg(&F[(size_t)sidx * 8 + lane]);
                a0.x = fmaf(v.x, w, a0.x); a0.y = fmaf(v.y, w, a0.y);
                a0.z = fmaf(v.z, w, a0.z); a0.w = fmaf(v.w, w, a0.w);
            }
        }
    }
    float4 acc = make_float4(a0.x + a1.x, a0.y + a1.y, a0.z + a1.z, a0.w + a1.w);

    float4 b = ((const float4*)b1)[lane];
    float4 q;
    q.x = dn * (dn * acc.x + b.x);
    q.y = dn * (dn * acc.y + b.y);
    q.z = dn * (dn * acc.z + b.z);
    q.w = dn * (dn * acc.w + b.w);
    ((float4*)g_q)[(size_t)node * 8 + lane] = q;
}

// ---------------------------------------------------------------------------
// Gather layer 2 + fused pooling (q is pre-scaled; plain sum)
// ---------------------------------------------------------------------------
__device__ __forceinline__ void red_add_v4(float* ptr, float4 v) {
    asm volatile("red.global.add.v4.f32 [%0], {%1, %2, %3, %4};"
                 :: "l"(ptr), "f"(v.x), "f"(v.y), "f"(v.z), "f"(v.w)
                 : "memory");
}

__global__ void __launch_bounds__(256) k_gather2(const void* __restrict__ batch, int N) {
    int node = blockIdx.x * 32 + (threadIdx.x >> 3);
    int lane = threadIdx.x & 7;
    if (node >= N) return;

    int deg = g_cur[node];
    int m = deg < CAP ? deg : CAP;
    const int4* bp4 = (const int4*)(g_bucket + (size_t)node * CAP);
    const float4* F = (const float4*)g_q;

    float4 a0 = __ldg(&F[(size_t)node * 8 + lane]);  // self (pre-scaled)
    float4 a1 = make_float4(0, 0, 0, 0);
    float4 a2 = make_float4(0, 0, 0, 0);
    float4 a3 = make_float4(0, 0, 0, 0);

    int e = 0;
    for (; e + 8 <= m; e += 8) {
        int4 ia = __ldg(&bp4[e >> 2]);
        int4 ib = __ldg(&bp4[(e >> 2) + 1]);
        float4 v0 = __ldg(&F[(size_t)ia.x * 8 + lane]);
        float4 v1 = __ldg(&F[(size_t)ia.y * 8 + lane]);
        float4 v2 = __ldg(&F[(size_t)ia.z * 8 + lane]);
        float4 v3 = __ldg(&F[(size_t)ia.w * 8 + lane]);
        float4 v4 = __ldg(&F[(size_t)ib.x * 8 + lane]);
        float4 v5 = __ldg(&F[(size_t)ib.y * 8 + lane]);
        float4 v6 = __ldg(&F[(size_t)ib.z * 8 + lane]);
        float4 v7 = __ldg(&F[(size_t)ib.w * 8 + lane]);
        a0.x += v0.x; a0.y += v0.y; a0.z += v0.z; a0.w += v0.w;
        a1.x += v1.x; a1.y += v1.y; a1.z += v1.z; a1.w += v1.w;
        a2.x += v2.x; a2.y += v2.y; a2.z += v2.z; a2.w += v2.w;
        a3.x += v3.x; a3.y += v3.y; a3.z += v3.z; a3.w += v3.w;
        a0.x += v4.x; a0.y += v4.y; a0.z += v4.z; a0.w += v4.w;
        a1.x += v5.x; a1.y += v5.y; a1.z += v5.z; a1.w += v5.w;
        a2.x += v6.x; a2.y += v6.y; a2.z += v6.z; a2.w += v6.w;
        a3.x += v7.x; a3.y += v7.y; a3.z += v7.z; a3.w += v7.w;
    }
    if (e + 4 <= m) {
        int4 ia = __ldg(&bp4[e >> 2]);
        float4 v0 = __ldg(&F[(size_t)ia.x * 8 + lane]);
        float4 v1 = __ldg(&F[(size_t)ia.y * 8 + lane]);
        float4 v2 = __ldg(&F[(size_t)ia.z * 8 + lane]);
        float4 v3 = __ldg(&F[(size_t)ia.w * 8 + lane]);
        a0.x += v0.x; a0.y += v0.y; a0.z += v0.z; a0.w += v0.w;
        a1.x += v1.x; a1.y += v1.y; a1.z += v1.z; a1.w += v1.w;
        a2.x += v2.x; a2.y += v2.y; a2.z += v2.z; a2.w += v2.w;
        a3.x += v3.x; a3.y += v3.y; a3.z += v3.z; a3.w += v3.w;
        e += 4;
    }
    const int* bp = (const int*)bp4;
    for (; e < m; e++) {
        int i0 = __ldg(&bp[e]);
        float4 v0 = __ldg(&F[(size_t)i0 * 8 + lane]);
        a0.x += v0.x; a0.y += v0.y; a0.z += v0.z; a0.w += v0.w;
    }
    if (deg > CAP) {
        int oc = g_ovf_cnt;
        for (int i = 0; i < oc; i++) {
            if (g_ovf_dst[i] == node) {
                float4 v = __ldg(&F[(size_t)g_ovf_src[i] * 8 + lane]);
                a0.x += v.x; a0.y += v.y; a0.z += v.z; a0.w += v.w;
            }
        }
    }
    a0.x += a1.x + a2.x + a3.x;
    a0.y += a1.y + a2.y + a3.y;
    a0.z += a1.z + a2.z + a3.z;
    a0.w += a1.w + a2.w + a3.w;

    float dn = rsqrtf(1.0f + (float)deg);
    float4 h = make_float4(dn * a0.x, dn * a0.y, dn * a0.z, dn * a0.w);
    int gidx = idx_get(batch, node, g_flags[1]);
    red_add_v4(g_pool + (size_t)gidx * C + lane * 4, h);
}

// ---------------------------------------------------------------------------
// Head (1 block, 2 threads/graph; lane pair tid=2g+h splits the GEMMs)
// ---------------------------------------------------------------------------
__global__ void k_head(const void* __restrict__ batch, int N,
                       const float* __restrict__ W2, const float* __restrict__ b2,
                       const float* __restrict__ fcW1, const float* __restrict__ fcb1,
                       const float* __restrict__ gamma, const float* __restrict__ beta,
                       const float* __restrict__ fcW2, const float* __restrict__ fcb2,
                       float* __restrict__ out, int G) {
    __shared__ float sW2[32 * 64];
    __shared__ float sF1[64 * 32];
    __shared__ float sfb1[32], sgam[32], sbet[32], sfw2[32];
    __shared__ float ssum[32], ssq[32];
    __shared__ float sfb2;

    int tid = threadIdx.x;
    int nthr = blockDim.x;
    for (int i = tid; i < 32 * 64; i += nthr) sW2[i] = W2[i];
    for (int i = tid; i < 64 * 32; i += nthr) sF1[i] = fcW1[i];
    if (tid < 32) {
        sfb1[tid] = fcb1[tid]; sgam[tid] = gamma[tid]; sbet[tid] = beta[tid];
        sfw2[tid] = fcW2[tid]; ssum[tid] = 0.0f; ssq[tid] = 0.0f;
    }
    if (tid == 0) sfb2 = fcb2[0];
    __syncthreads();

    int g = tid >> 1;        // graph
    int h = tid & 1;         // half: h=0 -> j in [0,32), h=1 -> j in [32,64)
    int is64 = g_flags[1];

    // node count of graph g
    int lo = 0, hi = N;
    while (lo < hi) { int m = (lo + hi) >> 1; if (idx_get(batch, m, is64) < g) lo = m + 1; else hi = m; }
    int start = lo;
    hi = N;
    while (lo < hi) { int m = (lo + hi) >> 1; if (idx_get(batch, m, is64) < g + 1) lo = m + 1; else hi = m; }
    int cnt = lo - start;
    float inv_cnt = 1.0f / (float)max(cnt, 1);

    float r[32];
#pragma unroll
    for (int i = 0; i < 32; i++) r[i] = g_pool[g * 32 + i] * inv_cnt;

    // o2 half: j = h*32 + j32
    float o2[32];
#pragma unroll
    for (int j = 0; j < 32; j++) o2[j] = __ldg(&b2[h * 32 + j]) * 0.5f;  // split bias
    for (int k = 0; k < 32; k++) {
        float rk = r[k];
        const float* wrow = sW2 + k * 64 + h * 32;
#pragma unroll
        for (int j = 0; j < 32; j++) o2[j] = fmaf(rk, wrow[j], o2[j]);
    }
    // NOTE: bias*0.5 trick is wrong for z partial sums only if relu applied
    // before combine -- we combine pre-relu, so each half carrying half the
    // b2 bias gives z = sum_j (o2_full[j]) * F1[j][i] exactly.

    // z partial over this half's 64-dim range
    float zz[32];
#pragma unroll
    for (int i = 0; i < 32; i++) zz[i] = 0.0f;
    for (int j = 0; j < 32; j++) {
        float oj = o2[j];
        const float* frow = sF1 + (h * 32 + j) * 32;
#pragma unroll
        for (int i = 0; i < 32; i++) zz[i] = fmaf(oj, frow[i], zz[i]);
    }

    // exchange halves within the lane pair and build z (h==0 lanes finalize)
    unsigned fullm = 0xFFFFFFFFu;
    float z[32];
#pragma unroll
    for (int i = 0; i < 32; i++) {
        float other = __shfl_xor_sync(fullm, zz[i], 1);
        z[i] = fmaxf(zz[i] + other + sfb1[i], 0.0f);
    }

    // BN stats over graphs: even lanes hold valid z for graph g.
    // Reduce across the 16 even lanes of each warp (offsets 2,4,8,16).
    for (int i = 0; i < 32; i++) {
        float v = (h == 0) ? z[i] : 0.0f;
        float v2 = v * v;
#pragma unroll
        for (int o = 2; o < 32; o <<= 1) {
            v += __shfl_down_sync(fullm, v, o);
            v2 += __shfl_down_sync(fullm, v2, o);
        }
        if ((tid & 31) == 0) { atomicAdd(&ssum[i], v); atomicAdd(&ssq[i], v2); }
    }
    __syncthreads();

    if (h == 0) {
        float acc = sfb2;
        float invG = 1.0f / (float)G;
#pragma unroll
        for (int i = 0; i < 32; i++) {
            float mu = ssum[i] * invG;
            float var = ssq[i] * invG - mu * mu;
            float zb = (z[i] - mu) * rsqrtf(var + 1e-5f) * sgam[i] + sbet[i];
            acc = fmaf(zb, sfw2[i], acc);
        }
        out[g] = fmaxf(acc, 0.0f) + log1pf(expf(-fabsf(acc)));
    }
}

// ---------------------------------------------------------------------------
extern "C" void kernel_launch(void* const* d_in, const int* in_sizes, int n_in,
                              void* d_out, int out_size) {
    const float* x     = (const float*)d_in[0];
    const void*  eidx  = d_in[1];
    const void*  batch = d_in[2];
    const float* W1    = (const float*)d_in[3];
    const float* b1    = (const float*)d_in[4];
    const float* W2    = (const float*)d_in[5];
    const float* b2    = (const float*)d_in[6];
    const float* fcW1  = (const float*)d_in[7];
    const float* fcb1  = (const float*)d_in[8];
    const float* gamma = (const float*)d_in[9];
    const float* beta  = (const float*)d_in[10];
    const float* fcW2  = (const float*)d_in[11];
    const float* fcb2  = (const float*)d_in[12];

    int N = in_sizes[0] / 128;
    int E = in_sizes[1] / 2;
    int G = out_size;

    void *pcur, *ppool;
    cudaGetSymbolAddress(&pcur, g_cur);
    cudaGetSymbolAddress(&ppool, g_pool);

    // Fork: branch B (s2) runs the GEMM, independent of the CSR build.
    cudaEventRecord(g_sp.ev_fork, 0);
    cudaStreamWaitEvent(g_sp.s2, g_sp.ev_fork, 0);
    k_gemm1<<<ceil_div(N, 256), 256, 0, g_sp.s2>>>(x, W1, N);
    cudaEventRecord(g_sp.ev_join, g_sp.s2);

    // Branch A: init + detect + place on the default stream.
    cudaMemsetAsync(pcur, 0, (size_t)N * sizeof(int));
    cudaMemsetAsync(ppool, 0, (size_t)G * C * sizeof(float));
    k_detect<<<1, 256>>>((const unsigned*)eidx, (long)2 * E,
                         (const unsigned*)batch, (long)N);
    k_place<<<ceil_div(E, 512), 256>>>(eidx, E);

    // Join and finish serial tail.
    cudaStreamWaitEvent(0, g_sp.ev_join, 0);
    k_gather1<<<ceil_div(N, 32), 256>>>(b1, N);
    k_gather2<<<ceil_div(N, 32), 256>>>(batch, N);
    k_head<<<1, 2 * G>>>(batch, N, W2, b2, fcW1, fcb1, gamma, beta, fcW2, fcb2,
                         (float*)d_out, G);
}

// round 10
// speedup vs baseline: 1.0222x; 1.0222x over previous
#include <cuda_runtime.h>
#include <cstdint>

// ---------------------------------------------------------------------------
// GCN via one-pass bucket-CSR gather, place || gemm via graph stream fork:
//   branch A: memsets, detect, place (bucket[dst*64+slot]=src; cur==degree)
//   branch B: p_raw = x @ W1            (independent of A)
//   join:     scale: dinv=rsqrt(1+deg); p = p_raw*dinv
//   gather1:  q[n] = dinv*(dinv*(sum p[nbr] + p[n]) + b1)
//   gather2:  h[n] = dinv*(sum q[nbr] + q[n]); pool[batch[n]] += h (red.v4)
//   head:     mean, @W2+b2, relu(@fcW1+fcb1), batchnorm, softplus(@fcW2+fcb2)
// ---------------------------------------------------------------------------

#define MAXN 100000
#define MAXE 1600000
#define MAXG 256
#define C 32
#define CAP 64

__device__ int   g_bucket[MAXN * CAP];
__device__ int   g_cur[MAXN];          // placement cursor == degree afterwards
__device__ int   g_ovf_dst[MAXE];
__device__ int   g_ovf_src[MAXE];
__device__ int   g_ovf_cnt;
__device__ float g_dinv[MAXN];
__device__ float g_p[MAXN * C];
__device__ float g_q[MAXN * C];
__device__ float g_pool[MAXG * C];
__device__ int   g_flags[2];           // [0]=edge_index int64, [1]=batch int64

static inline int ceil_div(int a, int b) { return (a + b - 1) / b; }

// Host-side stream/event objects (created once; host objects, no device mem)
struct StreamPack {
    cudaStream_t s2;
    cudaEvent_t ev_fork, ev_join;
    StreamPack() {
        cudaStreamCreateWithFlags(&s2, cudaStreamNonBlocking);
        cudaEventCreateWithFlags(&ev_fork, cudaEventDisableTiming);
        cudaEventCreateWithFlags(&ev_join, cudaEventDisableTiming);
    }
};
static StreamPack g_sp;

__device__ __forceinline__ int idx_get(const void* p, long i, int is64) {
    // int64 path: load only the low 32-bit word (values are < 2^31)
    return is64 ? ((const int*)p)[2 * i] : ((const int*)p)[i];
}

// ---------------------------------------------------------------------------
// dtype detect (zeroing handled by cudaMemsetAsync host-side)
// ---------------------------------------------------------------------------
__global__ void k_detect(const unsigned* __restrict__ e, long ewords,
                         const unsigned* __restrict__ b, long bwords) {
    __shared__ unsigned se, sb;
    if (threadIdx.x == 0) { se = 0u; sb = 0u; g_ovf_cnt = 0; }
    __syncthreads();
    unsigned a = 0u, c = 0u;
    long eh = ewords / 2, bh = bwords / 2;
    for (int s = 0; s < 16; s++) {
        long idx = (long)(threadIdx.x * 16 + s);
        long j = (idx * eh) / 4096;
        a |= e[2 * j + 1];
        long k = (idx * bh) / 4096;
        c |= b[2 * k + 1];
    }
    atomicOr(&se, a);
    atomicOr(&sb, c);
    __syncthreads();
    if (threadIdx.x == 0) {
        g_flags[0] = (se == 0u) ? 1 : 0;
        g_flags[1] = (sb == 0u) ? 1 : 0;
    }
}

// ---------------------------------------------------------------------------
// One-pass bucket placement, 2 independent edges/thread (batched).
// ---------------------------------------------------------------------------
__global__ void k_place(const void* __restrict__ eidx, int E) {
    int is64 = g_flags[0];
    int T = gridDim.x * blockDim.x;
    int tid = blockIdx.x * blockDim.x + threadIdx.x;

    int e0 = tid, e1 = tid + T;
    bool v0 = e0 < E, v1 = e1 < E;
    int s0 = 0, t0 = 0, s1 = 0, t1 = 0;
    if (v0) { s0 = idx_get(eidx, e0, is64); t0 = idx_get(eidx, (long)E + e0, is64); }
    if (v1) { s1 = idx_get(eidx, e1, is64); t1 = idx_get(eidx, (long)E + e1, is64); }

    int sl0 = 0, sl1 = 0;
    if (v0) sl0 = atomicAdd(&g_cur[t0], 1);
    if (v1) sl1 = atomicAdd(&g_cur[t1], 1);

    if (v0) {
        if (sl0 < CAP) g_bucket[(size_t)t0 * CAP + sl0] = s0;
        else { int o = atomicAdd(&g_ovf_cnt, 1); g_ovf_dst[o] = t0; g_ovf_src[o] = s0; }
    }
    if (v1) {
        if (sl1 < CAP) g_bucket[(size_t)t1 * CAP + sl1] = s1;
        else { int o = atomicAdd(&g_ovf_cnt, 1); g_ovf_dst[o] = t1; g_ovf_src[o] = s1; }
    }
}

// ---------------------------------------------------------------------------
// GEMM raw (packed fma.rn.f32x2): p_raw[n,:] = x[n,:] @ W1  (no dinv)
// ---------------------------------------------------------------------------
__global__ void __launch_bounds__(256) k_gemm1(const float* __restrict__ x,
                                               const float* __restrict__ W1, int N) {
    __shared__ unsigned long long sW[128 * 16];
    const unsigned long long* Wp = (const unsigned long long*)W1;
    for (int i = threadIdx.x; i < 128 * 16; i += 256) sW[i] = Wp[i];
    __syncthreads();

    int n = blockIdx.x * 256 + threadIdx.x;
    if (n >= N) return;

    unsigned long long acc[16];
#pragma unroll
    for (int j = 0; j < 16; j++) acc[j] = 0ull;

    const float4* xr = (const float4*)(x + (size_t)n * 128);
#pragma unroll 2
    for (int k4 = 0; k4 < 32; k4++) {
        float4 xv = __ldg(&xr[k4]);
        const float* xf = (const float*)&xv;
#pragma unroll
        for (int kk = 0; kk < 4; kk++) {
            unsigned xb = __float_as_uint(xf[kk]);
            unsigned long long xx;
            asm("mov.b64 %0, {%1, %1};" : "=l"(xx) : "r"(xb));
            const unsigned long long* wr = sW + (k4 * 4 + kk) * 16;
#pragma unroll
            for (int j = 0; j < 16; j++) {
                asm("fma.rn.f32x2 %0, %1, %2, %0;"
                    : "+l"(acc[j]) : "l"(xx), "l"(wr[j]));
            }
        }
    }
    unsigned long long* out = (unsigned long long*)(g_p + (size_t)n * C);
#pragma unroll
    for (int j = 0; j < 16; j++) out[j] = acc[j];
}

// ---------------------------------------------------------------------------
// scale: dinv = rsqrt(1+deg); p *= dinv   (two float4 per thread, same node)
// ---------------------------------------------------------------------------
__global__ void k_scale(int N) {
    int i = blockIdx.x * 256 + threadIdx.x;   // chunk pair id
    if (i >= N * 4) return;
    int n = i >> 2;
    float di = rsqrtf(1.0f + (float)g_cur[n]);
    if ((i & 3) == 0) g_dinv[n] = di;
    float4 v0 = ((const float4*)g_p)[2 * i];
    float4 v1 = ((const float4*)g_p)[2 * i + 1];
    v0.x *= di; v0.y *= di; v0.z *= di; v0.w *= di;
    v1.x *= di; v1.y *= di; v1.z *= di; v1.w *= di;
    ((float4*)g_p)[2 * i] = v0;
    ((float4*)g_p)[2 * i + 1] = v1;
}

// ---------------------------------------------------------------------------
// Gather core: 8 threads/node, lane owns one float4 chunk; int4 index loads.
// ---------------------------------------------------------------------------
__device__ __forceinline__ float4 gather_sum(const float4* __restrict__ F,
                                             int node, int lane) {
    int deg = g_cur[node];
    int m = deg < CAP ? deg : CAP;
    const int4* bp4 = (const int4*)(g_bucket + (size_t)node * CAP);

    float4 a0 = __ldg(&F[(size_t)node * 8 + lane]);  // self-loop
    float4 a1 = make_float4(0, 0, 0, 0);
    float4 a2 = make_float4(0, 0, 0, 0);
    float4 a3 = make_float4(0, 0, 0, 0);

    int e = 0;
    for (; e + 8 <= m; e += 8) {
        int4 ia = __ldg(&bp4[e >> 2]);
        int4 ib = __ldg(&bp4[(e >> 2) + 1]);
        float4 v0 = __ldg(&F[(size_t)ia.x * 8 + lane]);
        float4 v1 = __ldg(&F[(size_t)ia.y * 8 + lane]);
        float4 v2 = __ldg(&F[(size_t)ia.z * 8 + lane]);
        float4 v3 = __ldg(&F[(size_t)ia.w * 8 + lane]);
        float4 v4 = __ldg(&F[(size_t)ib.x * 8 + lane]);
        float4 v5 = __ldg(&F[(size_t)ib.y * 8 + lane]);
        float4 v6 = __ldg(&F[(size_t)ib.z * 8 + lane]);
        float4 v7 = __ldg(&F[(size_t)ib.w * 8 + lane]);
        a0.x += v0.x; a0.y += v0.y; a0.z += v0.z; a0.w += v0.w;
        a1.x += v1.x; a1.y += v1.y; a1.z += v1.z; a1.w += v1.w;
        a2.x += v2.x; a2.y += v2.y; a2.z += v2.z; a2.w += v2.w;
        a3.x += v3.x; a3.y += v3.y; a3.z += v3.z; a3.w += v3.w;
        a0.x += v4.x; a0.y += v4.y; a0.z += v4.z; a0.w += v4.w;
        a1.x += v5.x; a1.y += v5.y; a1.z += v5.z; a1.w += v5.w;
        a2.x += v6.x; a2.y += v6.y; a2.z += v6.z; a2.w += v6.w;
        a3.x += v7.x; a3.y += v7.y; a3.z += v7.z; a3.w += v7.w;
    }
    if (e + 4 <= m) {
        int4 ia = __ldg(&bp4[e >> 2]);
        float4 v0 = __ldg(&F[(size_t)ia.x * 8 + lane]);
        float4 v1 = __ldg(&F[(size_t)ia.y * 8 + lane]);
        float4 v2 = __ldg(&F[(size_t)ia.z * 8 + lane]);
        float4 v3 = __ldg(&F[(size_t)ia.w * 8 + lane]);
        a0.x += v0.x; a0.y += v0.y; a0.z += v0.z; a0.w += v0.w;
        a1.x += v1.x; a1.y += v1.y; a1.z += v1.z; a1.w += v1.w;
        a2.x += v2.x; a2.y += v2.y; a2.z += v2.z; a2.w += v2.w;
        a3.x += v3.x; a3.y += v3.y; a3.z += v3.z; a3.w += v3.w;
        e += 4;
    }
    const int* bp = (const int*)bp4;
    for (; e < m; e++) {
        int i0 = __ldg(&bp[e]);
        float4 v0 = __ldg(&F[(size_t)i0 * 8 + lane]);
        a0.x += v0.x; a0.y += v0.y; a0.z += v0.z; a0.w += v0.w;
    }
    if (deg > CAP) {   // exact overflow handling (normally empty)
        int oc = g_ovf_cnt;
        for (int i = 0; i < oc; i++) {
            if (g_ovf_dst[i] == node) {
                float4 v = __ldg(&F[(size_t)g_ovf_src[i] * 8 + lane]);
                a0.x += v.x; a0.y += v.y; a0.z += v.z; a0.w += v.w;
            }
        }
    }
    a0.x += a1.x + a2.x + a3.x;
    a0.y += a1.y + a2.y + a3.y;
    a0.z += a1.z + a2.z + a3.z;
    a0.w += a1.w + a2.w + a3.w;
    return a0;
}

// ---------------------------------------------------------------------------
// Gather layer 1: q = dinv*(dinv*sum + b1)
// ---------------------------------------------------------------------------
__global__ void __launch_bounds__(256, 6) k_gather1(const float* __restrict__ b1, int N) {
    int node = blockIdx.x * 32 + (threadIdx.x >> 3);
    int lane = threadIdx.x & 7;
    if (node >= N) return;

    float4 acc = gather_sum((const float4*)g_p, node, lane);

    float di = g_dinv[node];
    float4 b = ((const float4*)b1)[lane];
    float4 q;
    q.x = di * (di * acc.x + b.x);
    q.y = di * (di * acc.y + b.y);
    q.z = di * (di * acc.z + b.z);
    q.w = di * (di * acc.w + b.w);
    ((float4*)g_q)[(size_t)node * 8 + lane] = q;
}

// ---------------------------------------------------------------------------
// Gather layer 2 + fused pooling
// ---------------------------------------------------------------------------
__device__ __forceinline__ void red_add_v4(float* ptr, float4 v) {
    asm volatile("red.global.add.v4.f32 [%0], {%1, %2, %3, %4};"
                 :: "l"(ptr), "f"(v.x), "f"(v.y), "f"(v.z), "f"(v.w)
                 : "memory");
}

__global__ void __launch_bounds__(256, 6) k_gather2(const void* __restrict__ batch, int N) {
    int node = blockIdx.x * 32 + (threadIdx.x >> 3);
    int lane = threadIdx.x & 7;
    if (node >= N) return;

    float4 acc = gather_sum((const float4*)g_q, node, lane);

    float di = g_dinv[node];
    float4 h = make_float4(di * acc.x, di * acc.y, di * acc.z, di * acc.w);
    int gidx = idx_get(batch, node, g_flags[1]);
    red_add_v4(g_pool + (size_t)gidx * C + lane * 4, h);
}

// ---------------------------------------------------------------------------
// Head (1 block, 1 thread/graph)
// ---------------------------------------------------------------------------
__global__ void k_head(const void* __restrict__ batch, int N,
                       const float* __restrict__ W2, const float* __restrict__ b2,
                       const float* __restrict__ fcW1, const float* __restrict__ fcb1,
                       const float* __restrict__ gamma, const float* __restrict__ beta,
                       const float* __restrict__ fcW2, const float* __restrict__ fcb2,
                       float* __restrict__ out, int G) {
    __shared__ float sW2[32 * 64];
    __shared__ float sF1[64 * 32];
    __shared__ float sb2[64], sfb1[32], sgam[32], sbet[32], sfw2[32];
    __shared__ float ssum[32], ssq[32];
    __shared__ float sfb2;

    int tid = threadIdx.x;
    for (int i = tid; i < 32 * 64; i += blockDim.x) sW2[i] = W2[i];
    for (int i = tid; i < 64 * 32; i += blockDim.x) sF1[i] = fcW1[i];
    if (tid < 64) sb2[tid] = b2[tid];
    if (tid < 32) {
        sfb1[tid] = fcb1[tid]; sgam[tid] = gamma[tid]; sbet[tid] = beta[tid];
        sfw2[tid] = fcW2[tid]; ssum[tid] = 0.0f; ssq[tid] = 0.0f;
    }
    if (tid == 0) sfb2 = fcb2[0];
    __syncthreads();

    int g = tid;
    int is64 = g_flags[1];

    int lo = 0, hi = N;
    while (lo < hi) { int m = (lo + hi) >> 1; if (idx_get(batch, m, is64) < g) lo = m + 1; else hi = m; }
    int start = lo;
    hi = N;
    while (lo < hi) { int m = (lo + hi) >> 1; if (idx_get(batch, m, is64) < g + 1) lo = m + 1; else hi = m; }
    int cnt = lo - start;
    float inv_cnt = 1.0f / (float)max(cnt, 1);

    float r[32];
#pragma unroll
    for (int i = 0; i < 32; i++) r[i] = g_pool[g * 32 + i] * inv_cnt;

    float o2[64];
#pragma unroll
    for (int j = 0; j < 64; j++) o2[j] = sb2[j];
    for (int k = 0; k < 32; k++) {
        float rk = r[k];
#pragma unroll
        for (int j = 0; j < 64; j++) o2[j] = fmaf(rk, sW2[k * 64 + j], o2[j]);
    }

    float z[32];
#pragma unroll
    for (int i = 0; i < 32; i++) z[i] = sfb1[i];
    for (int j = 0; j < 64; j++) {
        float oj = o2[j];
#pragma unroll
        for (int i = 0; i < 32; i++) z[i] = fmaf(oj, sF1[j * 32 + i], z[i]);
    }
#pragma unroll
    for (int i = 0; i < 32; i++) z[i] = fmaxf(z[i], 0.0f);

    for (int i = 0; i < 32; i++) {
        float v = z[i], v2 = v * v;
#pragma unroll
        for (int o = 16; o > 0; o >>= 1) {
            v += __shfl_down_sync(0xFFFFFFFFu, v, o);
            v2 += __shfl_down_sync(0xFFFFFFFFu, v2, o);
        }
        if ((tid & 31) == 0) { atomicAdd(&ssum[i], v); atomicAdd(&ssq[i], v2); }
    }
    __syncthreads();

    float acc = sfb2;
    float invG = 1.0f / (float)G;
#pragma unroll
    for (int i = 0; i < 32; i++) {
        float mu = ssum[i] * invG;
        float var = ssq[i] * invG - mu * mu;
        float zb = (z[i] - mu) * rsqrtf(var + 1e-5f) * sgam[i] + sbet[i];
        acc = fmaf(zb, sfw2[i], acc);
    }
    out[g] = fmaxf(acc, 0.0f) + log1pf(expf(-fabsf(acc)));
}

// ---------------------------------------------------------------------------
extern "C" void kernel_launch(void* const* d_in, const int* in_sizes, int n_in,
                              void* d_out, int out_size) {
    const float* x     = (const float*)d_in[0];
    const void*  eidx  = d_in[1];
    const void*  batch = d_in[2];
    const float* W1    = (const float*)d_in[3];
    const float* b1    = (const float*)d_in[4];
    const float* W2    = (const float*)d_in[5];
    const float* b2    = (const float*)d_in[6];
    const float* fcW1  = (const float*)d_in[7];
    const float* fcb1  = (const float*)d_in[8];
    const float* gamma = (const float*)d_in[9];
    const float* beta  = (const float*)d_in[10];
    const float* fcW2  = (const float*)d_in[11];
    const float* fcb2  = (const float*)d_in[12];

    int N = in_sizes[0] / 128;
    int E = in_sizes[1] / 2;
    int G = out_size;

    void *pcur, *ppool;
    cudaGetSymbolAddress(&pcur, g_cur);
    cudaGetSymbolAddress(&ppool, g_pool);

    // Fork: branch B (s2) runs the GEMM, independent of the CSR build.
    cudaEventRecord(g_sp.ev_fork, 0);
    cudaStreamWaitEvent(g_sp.s2, g_sp.ev_fork, 0);
    k_gemm1<<<ceil_div(N, 256), 256, 0, g_sp.s2>>>(x, W1, N);
    cudaEventRecord(g_sp.ev_join, g_sp.s2);

    // Branch A: init + detect + place on the default stream.
    cudaMemsetAsync(pcur, 0, (size_t)N * sizeof(int));
    cudaMemsetAsync(ppool, 0, (size_t)G * C * sizeof(float));
    k_detect<<<1, 256>>>((const unsigned*)eidx, (long)2 * E,
                         (const unsigned*)batch, (long)N);
    k_place<<<ceil_div(E, 512), 256>>>(eidx, E);

    // Join and finish serial tail.
    cudaStreamWaitEvent(0, g_sp.ev_join, 0);
    k_scale<<<ceil_div(N * 4, 256), 256>>>(N);
    k_gather1<<<ceil_div(N, 32), 256>>>(b1, N);
    k_gather2<<<ceil_div(N, 32), 256>>>(batch, N);
    k_head<<<1, G>>>(batch, N, W2, b2, fcW1, fcb1, gamma, beta, fcW2, fcb2,
                     (float*)d_out, G);
}

// round 11
// speedup vs baseline: 1.0570x; 1.0340x over previous
#include <cuda_runtime.h>
#include <cstdint>

// ---------------------------------------------------------------------------
// GCN via one-pass bucket-CSR gather, place || gemm via graph stream fork:
//   branch A: memsets, detect, place (bucket[dst*64+slot]=src; cur==degree)
//   branch B: p_raw = x @ W1            (independent of A)
//   join:     scale: dinv=rsqrt(1+deg); p = p_raw*dinv
//   gather1:  q[n] = dinv*(dinv*(sum p[nbr] + p[n]) + b1)
//   gather2:  h[n] = dinv*(sum q[nbr] + q[n]); pool[batch[n]] += h (red.v4)
//   headA:    (8 blocks) z = relu((pool/cnt)@W2+b2)@fcW1+fcb1), BN partials
//   headB:    (1 block)  batchnorm + fc2 + softplus
// ---------------------------------------------------------------------------

#define MAXN 100000
#define MAXE 1600000
#define MAXG 256
#define C 32
#define CAP 64

__device__ int   g_bucket[MAXN * CAP];
__device__ int   g_cur[MAXN];          // placement cursor == degree afterwards
__device__ int   g_ovf_dst[MAXE];
__device__ int   g_ovf_src[MAXE];
__device__ int   g_ovf_cnt;
__device__ float g_dinv[MAXN];
__device__ float g_p[MAXN * C];
__device__ float g_q[MAXN * C];
__device__ float g_pool[MAXG * C];
__device__ float g_z[MAXG * 32];
__device__ float g_bnsum[32];
__device__ float g_bnsq[32];
__device__ int   g_flags[2];           // [0]=edge_index int64, [1]=batch int64

static inline int ceil_div(int a, int b) { return (a + b - 1) / b; }

// Host-side stream/event objects (created once; host objects, no device mem)
struct StreamPack {
    cudaStream_t s2;
    cudaEvent_t ev_fork, ev_join;
    StreamPack() {
        cudaStreamCreateWithFlags(&s2, cudaStreamNonBlocking);
        cudaEventCreateWithFlags(&ev_fork, cudaEventDisableTiming);
        cudaEventCreateWithFlags(&ev_join, cudaEventDisableTiming);
    }
};
static StreamPack g_sp;

__device__ __forceinline__ int idx_get(const void* p, long i, int is64) {
    // int64 path: load only the low 32-bit word (values are < 2^31)
    return is64 ? ((const int*)p)[2 * i] : ((const int*)p)[i];
}

// ---------------------------------------------------------------------------
// dtype detect + small scalar zero-inits
// ---------------------------------------------------------------------------
__global__ void k_detect(const unsigned* __restrict__ e, long ewords,
                         const unsigned* __restrict__ b, long bwords) {
    __shared__ unsigned se, sb;
    if (threadIdx.x == 0) { se = 0u; sb = 0u; g_ovf_cnt = 0; }
    if (threadIdx.x < 32) { g_bnsum[threadIdx.x] = 0.0f; g_bnsq[threadIdx.x] = 0.0f; }
    __syncthreads();
    unsigned a = 0u, c = 0u;
    long eh = ewords / 2, bh = bwords / 2;
    for (int s = 0; s < 16; s++) {
        long idx = (long)(threadIdx.x * 16 + s);
        long j = (idx * eh) / 4096;
        a |= e[2 * j + 1];
        long k = (idx * bh) / 4096;
        c |= b[2 * k + 1];
    }
    atomicOr(&se, a);
    atomicOr(&sb, c);
    __syncthreads();
    if (threadIdx.x == 0) {
        g_flags[0] = (se == 0u) ? 1 : 0;
        g_flags[1] = (sb == 0u) ? 1 : 0;
    }
}

// ---------------------------------------------------------------------------
// One-pass bucket placement, 4 independent edges/thread (batched), full grid.
// ---------------------------------------------------------------------------
__global__ void k_place(const void* __restrict__ eidx, int E) {
    int is64 = g_flags[0];
    int T = gridDim.x * blockDim.x;
    int tid = blockIdx.x * blockDim.x + threadIdx.x;

    int s[4], t[4], sl[4];
    bool v[4];
#pragma unroll
    for (int u = 0; u < 4; u++) {
        int e = tid + u * T;
        v[u] = e < E;
        if (v[u]) {
            s[u] = idx_get(eidx, e, is64);
            t[u] = idx_get(eidx, (long)E + e, is64);
        }
    }
#pragma unroll
    for (int u = 0; u < 4; u++) {
        if (v[u]) sl[u] = atomicAdd(&g_cur[t[u]], 1);
    }
#pragma unroll
    for (int u = 0; u < 4; u++) {
        if (v[u]) {
            if (sl[u] < CAP) g_bucket[(size_t)t[u] * CAP + sl[u]] = s[u];
            else { int o = atomicAdd(&g_ovf_cnt, 1); g_ovf_dst[o] = t[u]; g_ovf_src[o] = s[u]; }
        }
    }
}

// ---------------------------------------------------------------------------
// GEMM raw (packed fma.rn.f32x2): p_raw[n,:] = x[n,:] @ W1  (no dinv)
// ---------------------------------------------------------------------------
__global__ void __launch_bounds__(256) k_gemm1(const float* __restrict__ x,
                                               const float* __restrict__ W1, int N) {
    __shared__ unsigned long long sW[128 * 16];
    const unsigned long long* Wp = (const unsigned long long*)W1;
    for (int i = threadIdx.x; i < 128 * 16; i += 256) sW[i] = Wp[i];
    __syncthreads();

    int n = blockIdx.x * 256 + threadIdx.x;
    if (n >= N) return;

    unsigned long long acc[16];
#pragma unroll
    for (int j = 0; j < 16; j++) acc[j] = 0ull;

    const float4* xr = (const float4*)(x + (size_t)n * 128);
#pragma unroll 2
    for (int k4 = 0; k4 < 32; k4++) {
        float4 xv = __ldg(&xr[k4]);
        const float* xf = (const float*)&xv;
#pragma unroll
        for (int kk = 0; kk < 4; kk++) {
            unsigned xb = __float_as_uint(xf[kk]);
            unsigned long long xx;
            asm("mov.b64 %0, {%1, %1};" : "=l"(xx) : "r"(xb));
            const unsigned long long* wr = sW + (k4 * 4 + kk) * 16;
#pragma unroll
            for (int j = 0; j < 16; j++) {
                asm("fma.rn.f32x2 %0, %1, %2, %0;"
                    : "+l"(acc[j]) : "l"(xx), "l"(wr[j]));
            }
        }
    }
    unsigned long long* out = (unsigned long long*)(g_p + (size_t)n * C);
#pragma unroll
    for (int j = 0; j < 16; j++) out[j] = acc[j];
}

// ---------------------------------------------------------------------------
// scale: dinv = rsqrt(1+deg); p *= dinv   (two float4 per thread, same node)
// ---------------------------------------------------------------------------
__global__ void k_scale(int N) {
    int i = blockIdx.x * 256 + threadIdx.x;   // chunk pair id
    if (i >= N * 4) return;
    int n = i >> 2;
    float di = rsqrtf(1.0f + (float)g_cur[n]);
    if ((i & 3) == 0) g_dinv[n] = di;
    float4 v0 = ((const float4*)g_p)[2 * i];
    float4 v1 = ((const float4*)g_p)[2 * i + 1];
    v0.x *= di; v0.y *= di; v0.z *= di; v0.w *= di;
    v1.x *= di; v1.y *= di; v1.z *= di; v1.w *= di;
    ((float4*)g_p)[2 * i] = v0;
    ((float4*)g_p)[2 * i + 1] = v1;
}

// ---------------------------------------------------------------------------
// Gather core: 8 threads/node, lane owns one float4 chunk; int4 index loads.
// ---------------------------------------------------------------------------
__device__ __forceinline__ float4 gather_sum(const float4* __restrict__ F,
                                             int node, int lane) {
    int deg = g_cur[node];
    int m = deg < CAP ? deg : CAP;
    const int4* bp4 = (const int4*)(g_bucket + (size_t)node * CAP);

    float4 a0 = __ldg(&F[(size_t)node * 8 + lane]);  // self-loop
    float4 a1 = make_float4(0, 0, 0, 0);
    float4 a2 = make_float4(0, 0, 0, 0);
    float4 a3 = make_float4(0, 0, 0, 0);

    int e = 0;
    for (; e + 8 <= m; e += 8) {
        int4 ia = __ldg(&bp4[e >> 2]);
        int4 ib = __ldg(&bp4[(e >> 2) + 1]);
        float4 v0 = __ldg(&F[(size_t)ia.x * 8 + lane]);
        float4 v1 = __ldg(&F[(size_t)ia.y * 8 + lane]);
        float4 v2 = __ldg(&F[(size_t)ia.z * 8 + lane]);
        float4 v3 = __ldg(&F[(size_t)ia.w * 8 + lane]);
        float4 v4 = __ldg(&F[(size_t)ib.x * 8 + lane]);
        float4 v5 = __ldg(&F[(size_t)ib.y * 8 + lane]);
        float4 v6 = __ldg(&F[(size_t)ib.z * 8 + lane]);
        float4 v7 = __ldg(&F[(size_t)ib.w * 8 + lane]);
        a0.x += v0.x; a0.y += v0.y; a0.z += v0.z; a0.w += v0.w;
        a1.x += v1.x; a1.y += v1.y; a1.z += v1.z; a1.w += v1.w;
        a2.x += v2.x; a2.y += v2.y; a2.z += v2.z; a2.w += v2.w;
        a3.x += v3.x; a3.y += v3.y; a3.z += v3.z; a3.w += v3.w;
        a0.x += v4.x; a0.y += v4.y; a0.z += v4.z; a0.w += v4.w;
        a1.x += v5.x; a1.y += v5.y; a1.z += v5.z; a1.w += v5.w;
        a2.x += v6.x; a2.y += v6.y; a2.z += v6.z; a2.w += v6.w;
        a3.x += v7.x; a3.y += v7.y; a3.z += v7.z; a3.w += v7.w;
    }
    if (e + 4 <= m) {
        int4 ia = __ldg(&bp4[e >> 2]);
        float4 v0 = __ldg(&F[(size_t)ia.x * 8 + lane]);
        float4 v1 = __ldg(&F[(size_t)ia.y * 8 + lane]);
        float4 v2 = __ldg(&F[(size_t)ia.z * 8 + lane]);
        float4 v3 = __ldg(&F[(size_t)ia.w * 8 + lane]);
        a0.x += v0.x; a0.y += v0.y; a0.z += v0.z; a0.w += v0.w;
        a1.x += v1.x; a1.y += v1.y; a1.z += v1.z; a1.w += v1.w;
        a2.x += v2.x; a2.y += v2.y; a2.z += v2.z; a2.w += v2.w;
        a3.x += v3.x; a3.y += v3.y; a3.z += v3.z; a3.w += v3.w;
        e += 4;
    }
    const int* bp = (const int*)bp4;
    for (; e < m; e++) {
        int i0 = __ldg(&bp[e]);
        float4 v0 = __ldg(&F[(size_t)i0 * 8 + lane]);
        a0.x += v0.x; a0.y += v0.y; a0.z += v0.z; a0.w += v0.w;
    }
    if (deg > CAP) {   // exact overflow handling (normally empty)
        int oc = g_ovf_cnt;
        for (int i = 0; i < oc; i++) {
            if (g_ovf_dst[i] == node) {
                float4 v = __ldg(&F[(size_t)g_ovf_src[i] * 8 + lane]);
                a0.x += v.x; a0.y += v.y; a0.z += v.z; a0.w += v.w;
            }
        }
    }
    a0.x += a1.x + a2.x + a3.x;
    a0.y += a1.y + a2.y + a3.y;
    a0.z += a1.z + a2.z + a3.z;
    a0.w += a1.w + a2.w + a3.w;
    return a0;
}

// ---------------------------------------------------------------------------
// Gather layer 1: q = dinv*(dinv*sum + b1)
// ---------------------------------------------------------------------------
__global__ void __launch_bounds__(256) k_gather1(const float* __restrict__ b1, int N) {
    int node = blockIdx.x * 32 + (threadIdx.x >> 3);
    int lane = threadIdx.x & 7;
    if (node >= N) return;

    float4 acc = gather_sum((const float4*)g_p, node, lane);

    float di = g_dinv[node];
    float4 b = ((const float4*)b1)[lane];
    float4 q;
    q.x = di * (di * acc.x + b.x);
    q.y = di * (di * acc.y + b.y);
    q.z = di * (di * acc.z + b.z);
    q.w = di * (di * acc.w + b.w);
    ((float4*)g_q)[(size_t)node * 8 + lane] = q;
}

// ---------------------------------------------------------------------------
// Gather layer 2 + fused pooling
// ---------------------------------------------------------------------------
__device__ __forceinline__ void red_add_v4(float* ptr, float4 v) {
    asm volatile("red.global.add.v4.f32 [%0], {%1, %2, %3, %4};"
                 :: "l"(ptr), "f"(v.x), "f"(v.y), "f"(v.z), "f"(v.w)
                 : "memory");
}

__global__ void __launch_bounds__(256) k_gather2(const void* __restrict__ batch, int N) {
    int node = blockIdx.x * 32 + (threadIdx.x >> 3);
    int lane = threadIdx.x & 7;
    if (node >= N) return;

    float4 acc = gather_sum((const float4*)g_q, node, lane);

    float di = g_dinv[node];
    float4 h = make_float4(di * acc.x, di * acc.y, di * acc.z, di * acc.w);
    int gidx = idx_get(batch, node, g_flags[1]);
    red_add_v4(g_pool + (size_t)gidx * C + lane * 4, h);
}

// ---------------------------------------------------------------------------
// Head phase A (grid = ceil(G/32) blocks x 128 thr; 4 threads per graph):
//   z[g] = relu((pool[g]/cnt)@W2 + b2)@fcW1 + fcb1), BN partial sums.
// thread = (g_local = tid>>2, q = tid&3); q owns o2[q*16 .. q*16+16).
// ---------------------------------------------------------------------------
__global__ void k_headA(const void* __restrict__ batch, int N,
                        const float* __restrict__ W2, const float* __restrict__ b2,
                        const float* __restrict__ fcW1, const float* __restrict__ fcb1,
                        int G) {
    __shared__ float sW2[32 * 64];
    __shared__ float sF1[64 * 32];
    int tid = threadIdx.x;
    for (int i = tid; i < 2048; i += 128) { sW2[i] = W2[i]; sF1[i] = fcW1[i]; }
    __syncthreads();

    int gl = tid >> 2;
    int q = tid & 3;
    int g = blockIdx.x * 32 + gl;
    if (g >= G) return;
    int is64 = g_flags[1];

    // node count of graph g via binary searches (duplicated across quad)
    int lo = 0, hi = N;
    while (lo < hi) { int m = (lo + hi) >> 1; if (idx_get(batch, m, is64) < g) lo = m + 1; else hi = m; }
    int start = lo;
    hi = N;
    while (lo < hi) { int m = (lo + hi) >> 1; if (idx_get(batch, m, is64) < g + 1) lo = m + 1; else hi = m; }
    int cnt = lo - start;
    float inv_cnt = 1.0f / (float)max(cnt, 1);

    float r[32];
#pragma unroll
    for (int i = 0; i < 32; i++) r[i] = __ldg(&g_pool[g * 32 + i]) * inv_cnt;

    // o2 slice [q*16, q*16+16)
    float o2[16];
#pragma unroll
    for (int j = 0; j < 16; j++) o2[j] = __ldg(&b2[q * 16 + j]);
    for (int k = 0; k < 32; k++) {
        float rk = r[k];
        const float* wrow = sW2 + k * 64 + q * 16;
#pragma unroll
        for (int j = 0; j < 16; j++) o2[j] = fmaf(rk, wrow[j], o2[j]);
    }

    // z partial from this slice
    float zz[32];
#pragma unroll
    for (int i = 0; i < 32; i++) zz[i] = 0.0f;
    for (int j = 0; j < 16; j++) {
        float oj = o2[j];
        const float* frow = sF1 + (q * 16 + j) * 32;
#pragma unroll
        for (int i = 0; i < 32; i++) zz[i] = fmaf(oj, frow[i], zz[i]);
    }

    // combine quad partials (lanes 4k..4k+3 hold the same graph)
    unsigned fm = 0xFFFFFFFFu;
#pragma unroll
    for (int i = 0; i < 32; i++) {
        zz[i] += __shfl_xor_sync(fm, zz[i], 1);
        zz[i] += __shfl_xor_sync(fm, zz[i], 2);
    }

    // z = relu(sum + fcb1); store (q==0) and accumulate BN partials
    float z[32];
#pragma unroll
    for (int i = 0; i < 32; i++) z[i] = fmaxf(zz[i] + __ldg(&fcb1[i]), 0.0f);
    if (q == 0) {
#pragma unroll
        for (int i = 0; i < 32; i++) g_z[g * 32 + i] = z[i];
    }
    for (int i = 0; i < 32; i++) {
        float v = (q == 0) ? z[i] : 0.0f;
        float v2 = v * v;
#pragma unroll
        for (int o = 16; o > 0; o >>= 1) {
            v += __shfl_down_sync(fm, v, o);
            v2 += __shfl_down_sync(fm, v2, o);
        }
        if ((tid & 31) == 0) {
            atomicAdd(&g_bnsum[i], v);
            atomicAdd(&g_bnsq[i], v2);
        }
    }
}

// ---------------------------------------------------------------------------
// Head phase B (1 block, 1 thread/graph): batchnorm + fc2 + softplus
// ---------------------------------------------------------------------------
__global__ void k_headB(const float* __restrict__ gamma, const float* __restrict__ beta,
                        const float* __restrict__ fcW2, const float* __restrict__ fcb2,
                        float* __restrict__ out, int G) {
    __shared__ float smu[32], sis[32], sgam[32], sbet[32], sfw2[32];
    int tid = threadIdx.x;
    if (tid < 32) {
        float invG = 1.0f / (float)G;
        float mu = g_bnsum[tid] * invG;
        float var = g_bnsq[tid] * invG - mu * mu;
        smu[tid] = mu;
        sis[tid] = rsqrtf(var + 1e-5f);
        sgam[tid] = gamma[tid];
        sbet[tid] = beta[tid];
        sfw2[tid] = fcW2[tid];
    }
    __syncthreads();
    if (tid >= G) return;

    float acc = __ldg(&fcb2[0]);
#pragma unroll
    for (int i = 0; i < 32; i++) {
        float zb = (g_z[tid * 32 + i] - smu[i]) * sis[i] * sgam[i] + sbet[i];
        acc = fmaf(zb, sfw2[i], acc);
    }
    out[tid] = fmaxf(acc, 0.0f) + log1pf(expf(-fabsf(acc)));
}

// ---------------------------------------------------------------------------
extern "C" void kernel_launch(void* const* d_in, const int* in_sizes, int n_in,
                              void* d_out, int out_size) {
    const float* x     = (const float*)d_in[0];
    const void*  eidx  = d_in[1];
    const void*  batch = d_in[2];
    const float* W1    = (const float*)d_in[3];
    const float* b1    = (const float*)d_in[4];
    const float* W2    = (const float*)d_in[5];
    const float* b2    = (const float*)d_in[6];
    const float* fcW1  = (const float*)d_in[7];
    const float* fcb1  = (const float*)d_in[8];
    const float* gamma = (const float*)d_in[9];
    const float* beta  = (const float*)d_in[10];
    const float* fcW2  = (const float*)d_in[11];
    const float* fcb2  = (const float*)d_in[12];

    int N = in_sizes[0] / 128;
    int E = in_sizes[1] / 2;
    int G = out_size;

    void *pcur, *ppool;
    cudaGetSymbolAddress(&pcur, g_cur);
    cudaGetSymbolAddress(&ppool, g_pool);

    // Fork: branch B (s2) runs the GEMM, independent of the CSR build.
    cudaEventRecord(g_sp.ev_fork, 0);
    cudaStreamWaitEvent(g_sp.s2, g_sp.ev_fork, 0);
    k_gemm1<<<ceil_div(N, 256), 256, 0, g_sp.s2>>>(x, W1, N);
    cudaEventRecord(g_sp.ev_join, g_sp.s2);

    // Branch A: init + detect + place on the default stream.
    cudaMemsetAsync(pcur, 0, (size_t)N * sizeof(int));
    cudaMemsetAsync(ppool, 0, (size_t)G * C * sizeof(float));
    k_detect<<<1, 256>>>((const unsigned*)eidx, (long)2 * E,
                         (const unsigned*)batch, (long)N);
    k_place<<<ceil_div(E, 1024), 256>>>(eidx, E);

    // Join and finish serial tail.
    cudaStreamWaitEvent(0, g_sp.ev_join, 0);
    k_scale<<<ceil_div(N * 4, 256), 256>>>(N);
    k_gather1<<<ceil_div(N, 32), 256>>>(b1, N);
    k_gather2<<<ceil_div(N, 32), 256>>>(batch, N);
    k_headA<<<ceil_div(G, 32), 128>>>(batch, N, W2, b2, fcW1, fcb1, G);
    k_headB<<<1, G>>>(gamma, beta, fcW2, fcb2, (float*)d_out, G);
}